// round 1
// baseline (speedup 1.0000x reference)
#include <cuda_runtime.h>
#include <math.h>

// ---------------- problem constants ----------------
constexpr int kN0Src = 400000, kN0Dst = 32000, kE0 = 320000;
constexpr int kN1Src = 32000,  kN1Dst = 3200,  kE1 = 32000;
constexpr int kN2Src = 3200,   kN2Dst = 1024,  kE2 = 10240;
constexpr int kInF = 256, kHid = 256, kNCls = 47;

// ---------------- device scratch (no allocs allowed) ----------------
__device__ float g_agg0[kN0Dst * kHid];
__device__ float g_h0  [kN0Dst * kHid];
__device__ float g_agg1[kN1Dst * kHid];
__device__ float g_h1  [kN1Dst * kHid];
__device__ float g_agg2[kN2Dst * kHid];

__device__ int g_deg0[kN0Dst], g_cur0[kN0Dst], g_off0[kN0Dst + 1], g_es0[kE0];
__device__ int g_deg1[kN1Dst], g_cur1[kN1Dst], g_off1[kN1Dst + 1], g_es1[kE1];
__device__ int g_deg2[kN2Dst], g_cur2[kN2Dst], g_off2[kN2Dst + 1], g_es2[kE2];

// ---------------- kernels ----------------

__global__ void zero_counts_kernel() {
    int i = blockIdx.x * blockDim.x + threadIdx.x;
    if (i < kN0Dst) { g_deg0[i] = 0; g_cur0[i] = 0; }
    if (i < kN1Dst) { g_deg1[i] = 0; g_cur1[i] = 0; }
    if (i < kN2Dst) { g_deg2[i] = 0; g_cur2[i] = 0; }
}

__global__ void hist_kernel(const int* __restrict__ dst, int n, int* __restrict__ deg) {
    int i = blockIdx.x * blockDim.x + threadIdx.x;
    if (i < n) atomicAdd(&deg[dst[i]], 1);
}

// Single-block exclusive scan over n counters (n up to ~32k). off[n] = total.
__global__ void exscan_kernel(const int* __restrict__ cnt, int* __restrict__ off, int n) {
    __shared__ int warp_sums[32];
    __shared__ int s_carry;
    int tid = threadIdx.x, lane = tid & 31, wid = tid >> 5;
    if (tid == 0) s_carry = 0;
    __syncthreads();
    for (int base = 0; base < n; base += 1024) {
        int i = base + tid;
        int v = (i < n) ? cnt[i] : 0;
        int orig = v;
        #pragma unroll
        for (int d = 1; d < 32; d <<= 1) {
            int t = __shfl_up_sync(0xffffffffu, v, d);
            if (lane >= d) v += t;
        }
        if (lane == 31) warp_sums[wid] = v;
        __syncthreads();
        if (wid == 0) {
            int w = warp_sums[lane];
            #pragma unroll
            for (int d = 1; d < 32; d <<= 1) {
                int t = __shfl_up_sync(0xffffffffu, w, d);
                if (lane >= d) w += t;
            }
            warp_sums[lane] = w;
        }
        __syncthreads();
        int add = (wid > 0) ? warp_sums[wid - 1] : 0;
        int incl = v + add;
        if (i < n) off[i] = s_carry + incl - orig;  // exclusive prefix
        __syncthreads();
        if (tid == 1023) s_carry += incl;           // block total
        __syncthreads();
    }
    if (tid == 0) off[n] = s_carry;
}

__global__ void fill_kernel(const int* __restrict__ src, const int* __restrict__ dst, int n,
                            const int* __restrict__ off, int* __restrict__ cursor,
                            int* __restrict__ esrc) {
    int i = blockIdx.x * blockDim.x + threadIdx.x;
    if (i < n) {
        int d = dst[i];
        int p = atomicAdd(&cursor[d], 1);
        esrc[off[d] + p] = src[i];
    }
}

// One warp per destination node: mean of gathered 256-float rows.
__global__ void aggregate_kernel(const float* __restrict__ feat, const int* __restrict__ off,
                                 const int* __restrict__ esrc, float* __restrict__ agg,
                                 int n_dst) {
    int warp = (blockIdx.x * blockDim.x + threadIdx.x) >> 5;
    int lane = threadIdx.x & 31;
    if (warp >= n_dst) return;
    int s = off[warp], e = off[warp + 1];
    float4 a0 = make_float4(0.f, 0.f, 0.f, 0.f);
    float4 a1 = make_float4(0.f, 0.f, 0.f, 0.f);
    for (int i = s; i < e; i++) {
        const float4* row = (const float4*)(feat + (size_t)esrc[i] * 256);
        float4 v0 = __ldg(&row[lane]);
        float4 v1 = __ldg(&row[lane + 32]);
        a0.x += v0.x; a0.y += v0.y; a0.z += v0.z; a0.w += v0.w;
        a1.x += v1.x; a1.y += v1.y; a1.z += v1.z; a1.w += v1.w;
    }
    int deg = e - s;
    float inv = 1.0f / (float)(deg > 1 ? deg : 1);
    a0.x *= inv; a0.y *= inv; a0.z *= inv; a0.w *= inv;
    a1.x *= inv; a1.y *= inv; a1.z *= inv; a1.w *= inv;
    float4* dp = (float4*)(agg + (size_t)warp * 256);
    dp[lane]      = a0;
    dp[lane + 32] = a1;
}

// C[M,N] = act(A[M,K] @ B[K,N] + bias).  M%128==0, N%128==0, K%16==0.
template <int RELU>
__global__ void __launch_bounds__(256)
gemm_bias_kernel(const float* __restrict__ A, const float* __restrict__ B,
                 const float* __restrict__ bias, float* __restrict__ C,
                 int M, int N, int K) {
    constexpr int BM = 128, BN = 128, BK = 16;
    __shared__ float As[BK][BM + 4];
    __shared__ float Bs[BK][BN];
    int tid = threadIdx.x;
    const float* Ab = A + (size_t)blockIdx.y * BM * K;
    const float* Bb = B + (size_t)blockIdx.x * BN;

    float acc[8][8];
    #pragma unroll
    for (int i = 0; i < 8; i++)
        #pragma unroll
        for (int j = 0; j < 8; j++) acc[i][j] = 0.f;

    int ar = tid >> 2;          // 0..63
    int ac = (tid & 3) << 2;    // 0,4,8,12
    int br = tid >> 5;          // 0..7
    int bc = (tid & 31) << 2;   // 0..124
    int ty = (tid >> 4) << 3;   // 0..120
    int tx = (tid & 15) << 3;   // 0..120

    for (int k0 = 0; k0 < K; k0 += BK) {
        #pragma unroll
        for (int i = 0; i < 2; i++) {
            float4 v = *(const float4*)(Ab + (size_t)(ar + i * 64) * K + k0 + ac);
            As[ac + 0][ar + i * 64] = v.x;
            As[ac + 1][ar + i * 64] = v.y;
            As[ac + 2][ar + i * 64] = v.z;
            As[ac + 3][ar + i * 64] = v.w;
        }
        #pragma unroll
        for (int i = 0; i < 2; i++) {
            *(float4*)&Bs[br + i * 8][bc] =
                *(const float4*)(Bb + (size_t)(k0 + br + i * 8) * N + bc);
        }
        __syncthreads();
        #pragma unroll
        for (int kk = 0; kk < BK; kk++) {
            float a[8], b[8];
            *(float4*)&a[0] = *(const float4*)&As[kk][ty];
            *(float4*)&a[4] = *(const float4*)&As[kk][ty + 4];
            *(float4*)&b[0] = *(const float4*)&Bs[kk][tx];
            *(float4*)&b[4] = *(const float4*)&Bs[kk][tx + 4];
            #pragma unroll
            for (int i = 0; i < 8; i++)
                #pragma unroll
                for (int j = 0; j < 8; j++)
                    acc[i][j] += a[i] * b[j];
        }
        __syncthreads();
    }

    int row0 = blockIdx.y * BM + ty;
    int col0 = blockIdx.x * BN + tx;
    float bv[8];
    *(float4*)&bv[0] = *(const float4*)(bias + col0);
    *(float4*)&bv[4] = *(const float4*)(bias + col0 + 4);
    #pragma unroll
    for (int i = 0; i < 8; i++) {
        float o[8];
        #pragma unroll
        for (int j = 0; j < 8; j++) {
            float v = acc[i][j] + bv[j];
            o[j] = RELU ? fmaxf(v, 0.f) : v;
        }
        *(float4*)(C + (size_t)(row0 + i) * N + col0)     = *(float4*)&o[0];
        *(float4*)(C + (size_t)(row0 + i) * N + col0 + 4) = *(float4*)&o[4];
    }
}

// Final layer: logits = agg @ W2 + b2, then log_softmax. One block (64 thr) per row.
__global__ void layer2_logsoftmax_kernel(const float* __restrict__ agg,
                                         const float* __restrict__ W,
                                         const float* __restrict__ b,
                                         float* __restrict__ out) {
    __shared__ float a[256];
    __shared__ float logits[kNCls];
    __shared__ float s_ls;
    int row = blockIdx.x;
    int tid = threadIdx.x;
    const float4* ap = (const float4*)(agg + (size_t)row * 256);
    ((float4*)a)[tid] = ap[tid];
    __syncthreads();
    if (tid < kNCls) {
        float sum = b[tid];
        #pragma unroll 8
        for (int k = 0; k < 256; k++) sum += a[k] * W[k * kNCls + tid];
        logits[tid] = sum;
    }
    __syncthreads();
    if (tid == 0) {
        float m = -INFINITY;
        for (int j = 0; j < kNCls; j++) m = fmaxf(m, logits[j]);
        float s = 0.f;
        for (int j = 0; j < kNCls; j++) s += expf(logits[j] - m);
        s_ls = m + logf(s);
    }
    __syncthreads();
    if (tid < kNCls) out[(size_t)row * kNCls + tid] = logits[tid] - s_ls;
}

// ---------------- host launcher ----------------
extern "C" void kernel_launch(void* const* d_in, const int* in_sizes, int n_in,
                              void* d_out, int out_size) {
    const float* x    = (const float*)d_in[0];
    const float* W0   = (const float*)d_in[1];
    const float* b0   = (const float*)d_in[2];
    const float* W1   = (const float*)d_in[3];
    const float* b1   = (const float*)d_in[4];
    const float* W2   = (const float*)d_in[5];
    const float* b2   = (const float*)d_in[6];
    const int*   src0 = (const int*)d_in[7];
    const int*   dst0 = (const int*)d_in[8];
    const int*   src1 = (const int*)d_in[9];
    const int*   dst1 = (const int*)d_in[10];
    const int*   src2 = (const int*)d_in[11];
    const int*   dst2 = (const int*)d_in[12];
    float* out = (float*)d_out;

    float *agg0, *h0, *agg1, *h1, *agg2;
    int *deg0, *cur0, *off0, *es0;
    int *deg1, *cur1, *off1, *es1;
    int *deg2, *cur2, *off2, *es2;
    cudaGetSymbolAddress((void**)&agg0, g_agg0);
    cudaGetSymbolAddress((void**)&h0,   g_h0);
    cudaGetSymbolAddress((void**)&agg1, g_agg1);
    cudaGetSymbolAddress((void**)&h1,   g_h1);
    cudaGetSymbolAddress((void**)&agg2, g_agg2);
    cudaGetSymbolAddress((void**)&deg0, g_deg0);
    cudaGetSymbolAddress((void**)&cur0, g_cur0);
    cudaGetSymbolAddress((void**)&off0, g_off0);
    cudaGetSymbolAddress((void**)&es0,  g_es0);
    cudaGetSymbolAddress((void**)&deg1, g_deg1);
    cudaGetSymbolAddress((void**)&cur1, g_cur1);
    cudaGetSymbolAddress((void**)&off1, g_off1);
    cudaGetSymbolAddress((void**)&es1,  g_es1);
    cudaGetSymbolAddress((void**)&deg2, g_deg2);
    cudaGetSymbolAddress((void**)&cur2, g_cur2);
    cudaGetSymbolAddress((void**)&off2, g_off2);
    cudaGetSymbolAddress((void**)&es2,  g_es2);

    // CSR build (feature-independent)
    zero_counts_kernel<<<(kN0Dst + 255) / 256, 256>>>();
    hist_kernel<<<(kE0 + 255) / 256, 256>>>(dst0, kE0, deg0);
    hist_kernel<<<(kE1 + 255) / 256, 256>>>(dst1, kE1, deg1);
    hist_kernel<<<(kE2 + 255) / 256, 256>>>(dst2, kE2, deg2);
    exscan_kernel<<<1, 1024>>>(deg0, off0, kN0Dst);
    exscan_kernel<<<1, 1024>>>(deg1, off1, kN1Dst);
    exscan_kernel<<<1, 1024>>>(deg2, off2, kN2Dst);
    fill_kernel<<<(kE0 + 255) / 256, 256>>>(src0, dst0, kE0, off0, cur0, es0);
    fill_kernel<<<(kE1 + 255) / 256, 256>>>(src1, dst1, kE1, off1, cur1, es1);
    fill_kernel<<<(kE2 + 255) / 256, 256>>>(src2, dst2, kE2, off2, cur2, es2);

    // Layer 0
    aggregate_kernel<<<(kN0Dst * 32 + 255) / 256, 256>>>(x, off0, es0, agg0, kN0Dst);
    {
        dim3 grid(kHid / 128, kN0Dst / 128);
        gemm_bias_kernel<1><<<grid, 256>>>(agg0, W0, b0, h0, kN0Dst, kHid, kInF);
    }
    // Layer 1
    aggregate_kernel<<<(kN1Dst * 32 + 255) / 256, 256>>>(h0, off1, es1, agg1, kN1Dst);
    {
        dim3 grid(kHid / 128, kN1Dst / 128);
        gemm_bias_kernel<1><<<grid, 256>>>(agg1, W1, b1, h1, kN1Dst, kHid, kHid);
    }
    // Layer 2 + log_softmax
    aggregate_kernel<<<(kN2Dst * 32 + 255) / 256, 256>>>(h1, off2, es2, agg2, kN2Dst);
    layer2_logsoftmax_kernel<<<kN2Dst, 64>>>(agg2, W2, b2, out);

    (void)in_sizes; (void)n_in; (void)out_size;
}

// round 3
// speedup vs baseline: 1.4233x; 1.4233x over previous
#include <cuda_runtime.h>
#include <cuda_bf16.h>
#include <math.h>
#include <stdint.h>

// ---------------- problem constants ----------------
constexpr int kN0Src = 400000, kN0Dst = 32000, kE0 = 320000;
constexpr int kN1Src = 32000,  kN1Dst = 3200,  kE1 = 32000;
constexpr int kN2Src = 3200,   kN2Dst = 1024,  kE2 = 10240;
constexpr int kInF = 256, kHid = 256, kNCls = 47;

// ---------------- device scratch (no allocs allowed) ----------------
__device__ __align__(256) float g_h0  [kN0Dst * kHid];
__device__ __align__(256) float g_h1  [kN1Dst * kHid];
__device__ __align__(256) float g_agg2[kN2Dst * kHid];

// bf16 hi/lo split GEMM inputs (reused by layer 0 and layer 1; stream-ordered)
__device__ __align__(256) __nv_bfloat16 g_a_hi[kN0Dst * kHid];
__device__ __align__(256) __nv_bfloat16 g_a_lo[kN0Dst * kHid];
// transposed + split weights: Wt[n][k]
__device__ __align__(256) __nv_bfloat16 g_w0h[kHid * kHid], g_w0l[kHid * kHid];
__device__ __align__(256) __nv_bfloat16 g_w1h[kHid * kHid], g_w1l[kHid * kHid];

__device__ int g_deg0[kN0Dst], g_cur0[kN0Dst], g_off0[kN0Dst + 1], g_es0[kE0];
__device__ int g_deg1[kN1Dst], g_cur1[kN1Dst], g_off1[kN1Dst + 1], g_es1[kE1];
__device__ int g_deg2[kN2Dst], g_cur2[kN2Dst], g_off2[kN2Dst + 1], g_es2[kE2];

// ---------------- warp MMA helpers (sm_80+ ISA, safe on sm_100 baseline) -------
__device__ __forceinline__ uint32_t smem_u32(const void* p) {
    uint32_t a;
    asm("{ .reg .u64 t; cvta.to.shared.u64 t, %1; cvt.u32.u64 %0, t; }" : "=r"(a) : "l"(p));
    return a;
}

__device__ __forceinline__ void ldsm_x4(uint32_t& r0, uint32_t& r1, uint32_t& r2,
                                        uint32_t& r3, uint32_t addr) {
    asm volatile("ldmatrix.sync.aligned.m8n8.x4.shared.b16 {%0,%1,%2,%3}, [%4];"
                 : "=r"(r0), "=r"(r1), "=r"(r2), "=r"(r3) : "r"(addr));
}

__device__ __forceinline__ void mma16816(float c[4], uint32_t a0, uint32_t a1,
                                         uint32_t a2, uint32_t a3,
                                         uint32_t b0, uint32_t b1) {
    asm volatile(
        "mma.sync.aligned.m16n8k16.row.col.f32.bf16.bf16.f32 "
        "{%0,%1,%2,%3},{%4,%5,%6,%7},{%8,%9},{%0,%1,%2,%3};"
        : "+f"(c[0]), "+f"(c[1]), "+f"(c[2]), "+f"(c[3])
        : "r"(a0), "r"(a1), "r"(a2), "r"(a3), "r"(b0), "r"(b1));
}

// ---------------- CSR build ----------------
__global__ void zero_counts_kernel() {
    int i = blockIdx.x * blockDim.x + threadIdx.x;
    if (i < kN0Dst) { g_deg0[i] = 0; g_cur0[i] = 0; }
    if (i < kN1Dst) { g_deg1[i] = 0; g_cur1[i] = 0; }
    if (i < kN2Dst) { g_deg2[i] = 0; g_cur2[i] = 0; }
}

__global__ void hist3_kernel(const int* __restrict__ d0, const int* __restrict__ d1,
                             const int* __restrict__ d2) {
    int i = blockIdx.x * blockDim.x + threadIdx.x;
    if (i < kE0) atomicAdd(&g_deg0[d0[i]], 1);
    if (i < kE1) atomicAdd(&g_deg1[d1[i]], 1);
    if (i < kE2) atomicAdd(&g_deg2[d2[i]], 1);
}

__global__ void exscan3_kernel() {
    const int* cnt; int* off; int n;
    if (blockIdx.x == 0)      { cnt = g_deg0; off = g_off0; n = kN0Dst; }
    else if (blockIdx.x == 1) { cnt = g_deg1; off = g_off1; n = kN1Dst; }
    else                      { cnt = g_deg2; off = g_off2; n = kN2Dst; }
    __shared__ int warp_sums[32];
    __shared__ int s_carry;
    int tid = threadIdx.x, lane = tid & 31, wid = tid >> 5;
    if (tid == 0) s_carry = 0;
    __syncthreads();
    for (int base = 0; base < n; base += 1024) {
        int i = base + tid;
        int v = (i < n) ? cnt[i] : 0;
        int orig = v;
        #pragma unroll
        for (int d = 1; d < 32; d <<= 1) {
            int t = __shfl_up_sync(0xffffffffu, v, d);
            if (lane >= d) v += t;
        }
        if (lane == 31) warp_sums[wid] = v;
        __syncthreads();
        if (wid == 0) {
            int w = warp_sums[lane];
            #pragma unroll
            for (int d = 1; d < 32; d <<= 1) {
                int t = __shfl_up_sync(0xffffffffu, w, d);
                if (lane >= d) w += t;
            }
            warp_sums[lane] = w;
        }
        __syncthreads();
        int add = (wid > 0) ? warp_sums[wid - 1] : 0;
        int incl = v + add;
        if (i < n) off[i] = s_carry + incl - orig;
        __syncthreads();
        if (tid == 1023) s_carry += incl;
        __syncthreads();
    }
    if (tid == 0) off[n] = s_carry;
}

__global__ void fill3_kernel(const int* __restrict__ s0, const int* __restrict__ d0,
                             const int* __restrict__ s1, const int* __restrict__ d1,
                             const int* __restrict__ s2, const int* __restrict__ d2) {
    int i = blockIdx.x * blockDim.x + threadIdx.x;
    if (i < kE0) { int d = d0[i]; int p = atomicAdd(&g_cur0[d], 1); g_es0[g_off0[d] + p] = s0[i]; }
    if (i < kE1) { int d = d1[i]; int p = atomicAdd(&g_cur1[d], 1); g_es1[g_off1[d] + p] = s1[i]; }
    if (i < kE2) { int d = d2[i]; int p = atomicAdd(&g_cur2[d], 1); g_es2[g_off2[d] + p] = s2[i]; }
}

// ---------------- weight transpose + bf16 hi/lo split -------------------------
// Wt_hi[n][k] = hi(W[k][n]), Wt_lo[n][k] = lo(W[k][n]); W is 256x256 f32.
__global__ void wconv_kernel(const float* __restrict__ W0, const float* __restrict__ W1) {
    int i = blockIdx.x * blockDim.x + threadIdx.x;
    const float* W = (i < 65536) ? W0 : W1;
    __nv_bfloat16* wh = (i < 65536) ? g_w0h : g_w1h;
    __nv_bfloat16* wl = (i < 65536) ? g_w0l : g_w1l;
    int j = i & 65535;
    int k = j >> 8, n = j & 255;
    float v = W[j];
    __nv_bfloat16 hi = __float2bfloat16(v);
    __nv_bfloat16 lo = __float2bfloat16(v - __bfloat162float(hi));
    wh[n * 256 + k] = hi;
    wl[n * 256 + k] = lo;
}

// ---------------- aggregation (warp per dst, mean of 256-f rows) --------------
// BF16OUT=1: write bf16 hi/lo (GEMM input). BF16OUT=0: write f32 (layer 2).
template <int BF16OUT>
__global__ void aggregate_kernel(const float* __restrict__ feat, const int* __restrict__ off,
                                 const int* __restrict__ esrc, float* __restrict__ aggf,
                                 __nv_bfloat16* __restrict__ ah, __nv_bfloat16* __restrict__ al,
                                 int n_dst) {
    int warp = (blockIdx.x * blockDim.x + threadIdx.x) >> 5;
    int lane = threadIdx.x & 31;
    if (warp >= n_dst) return;
    int s = off[warp], e = off[warp + 1];
    float4 a0 = make_float4(0.f, 0.f, 0.f, 0.f);
    float4 a1 = make_float4(0.f, 0.f, 0.f, 0.f);
    for (int i = s; i < e; i++) {
        const float4* row = (const float4*)(feat + (size_t)esrc[i] * 256);
        float4 v0 = __ldg(&row[lane]);
        float4 v1 = __ldg(&row[lane + 32]);
        a0.x += v0.x; a0.y += v0.y; a0.z += v0.z; a0.w += v0.w;
        a1.x += v1.x; a1.y += v1.y; a1.z += v1.z; a1.w += v1.w;
    }
    int deg = e - s;
    float inv = 1.0f / (float)(deg > 1 ? deg : 1);
    a0.x *= inv; a0.y *= inv; a0.z *= inv; a0.w *= inv;
    a1.x *= inv; a1.y *= inv; a1.z *= inv; a1.w *= inv;
    if (BF16OUT) {
        float v[8] = {a0.x, a0.y, a0.z, a0.w, a1.x, a1.y, a1.z, a1.w};
        #pragma unroll
        for (int g = 0; g < 2; g++) {
            __nv_bfloat162 h01, h23, l01, l23;
            h01.x = __float2bfloat16(v[g*4+0]); h01.y = __float2bfloat16(v[g*4+1]);
            h23.x = __float2bfloat16(v[g*4+2]); h23.y = __float2bfloat16(v[g*4+3]);
            l01.x = __float2bfloat16(v[g*4+0] - __bfloat162float(h01.x));
            l01.y = __float2bfloat16(v[g*4+1] - __bfloat162float(h01.y));
            l23.x = __float2bfloat16(v[g*4+2] - __bfloat162float(h23.x));
            l23.y = __float2bfloat16(v[g*4+3] - __bfloat162float(h23.y));
            size_t base = (size_t)warp * 256 + g * 128 + lane * 4;
            *(__nv_bfloat162*)(ah + base)     = h01;
            *(__nv_bfloat162*)(ah + base + 2) = h23;
            *(__nv_bfloat162*)(al + base)     = l01;
            *(__nv_bfloat162*)(al + base + 2) = l23;
        }
    } else {
        float4* dp = (float4*)(aggf + (size_t)warp * 256);
        dp[lane]      = a0;
        dp[lane + 32] = a1;
    }
}

// ---------------- bf16 mma.sync GEMM with 3-product split ---------------------
// C[M,256] = relu(A @ W + bias); A given as hi/lo bf16 [M][256], W as Wt hi/lo [256][256].
// CTA: 128(M) x 128(N), K chunks of 64. 8 warps = 4(M) x 2(N); warp tile 32x64.
constexpr int SA_HI = 0;
constexpr int SA_LO = 16384;
constexpr int SB_HI = 32768;
constexpr int SB_LO = 49152;
constexpr int kGemmSmem = 65536;

__global__ void __launch_bounds__(256)
gemm_mma_relu_kernel(const __nv_bfloat16* __restrict__ Ah, const __nv_bfloat16* __restrict__ Al,
                     const __nv_bfloat16* __restrict__ Bh, const __nv_bfloat16* __restrict__ Bl,
                     const float* __restrict__ bias, float* __restrict__ C) {
    extern __shared__ char smem[];
    uint32_t sb = smem_u32(smem);
    int tid = threadIdx.x, warp = tid >> 5, lane = tid & 31;
    int m0 = blockIdx.x * 128;
    int n0 = blockIdx.y * 128;
    int wm = (warp & 3) * 32;   // warp M offset in tile
    int wn = (warp >> 2) * 64;  // warp N offset in tile

    float acc[2][8][4];
    #pragma unroll
    for (int i = 0; i < 2; i++)
        #pragma unroll
        for (int j = 0; j < 8; j++)
            #pragma unroll
            for (int q = 0; q < 4; q++) acc[i][j][q] = 0.f;

    // ldmatrix per-thread address bases (SW128 swizzle: XOR bits[6:4] by row%8)
    uint32_t xorv = (uint32_t)(lane & 7) << 4;
    // A fragment rows: groups 0:m0-7/k0, 1:m8-15/k0, 2:m0-7/k+16B, 3:m8-15/k+16B
    int rowA = wm + (lane & 7) + ((lane >> 3) & 1) * 8;
    uint32_t kbA = ((lane >> 4) & 1) << 4;
    uint32_t pA0 = sb + SA_HI + (uint32_t)(rowA)      * 128;
    uint32_t pA1 = sb + SA_HI + (uint32_t)(rowA + 16) * 128;
    // B fragment rows: groups 0:n0-7/k0, 1:n0-7/k+16B, 2:n8-15/k0, 3:n8-15/k+16B
    int rowB = wn + (lane & 7) + ((lane >> 4) & 1) * 8;
    uint32_t kbB = ((lane >> 3) & 1) << 4;
    uint32_t pB[4];
    #pragma unroll
    for (int j16 = 0; j16 < 4; j16++)
        pB[j16] = sb + SB_HI + (uint32_t)(rowB + j16 * 16) * 128;

    #pragma unroll 1
    for (int kc = 0; kc < 4; kc++) {
        // ---- load chunk: A rows m0..m0+127, B(Wt) rows n0..n0+127, k in [kc*64, +64)
        #pragma unroll
        for (int u = tid; u < 1024; u += 256) {
            int row = u >> 3;
            uint32_t c16 = (u & 7) << 4;                       // byte col within 128B row
            uint32_t so = (uint32_t)row * 128 + (c16 ^ ((row & 7) << 4));
            size_t ga = (size_t)(m0 + row) * 256 + kc * 64 + (c16 >> 1);
            size_t gb = (size_t)(n0 + row) * 256 + kc * 64 + (c16 >> 1);
            *(uint4*)(smem + SA_HI + so) = *(const uint4*)(Ah + ga);
            *(uint4*)(smem + SA_LO + so) = *(const uint4*)(Al + ga);
            *(uint4*)(smem + SB_HI + so) = *(const uint4*)(Bh + gb);
            *(uint4*)(smem + SB_LO + so) = *(const uint4*)(Bl + gb);
        }
        __syncthreads();

        #pragma unroll
        for (int kk = 0; kk < 4; kk++) {
            uint32_t koA = ((uint32_t)kk * 32 + kbA) ^ xorv;
            uint32_t koB = ((uint32_t)kk * 32 + kbB) ^ xorv;
            uint32_t ah[2][4], al[2][4];
            ldsm_x4(ah[0][0], ah[0][1], ah[0][2], ah[0][3], pA0 + koA);
            ldsm_x4(ah[1][0], ah[1][1], ah[1][2], ah[1][3], pA1 + koA);
            ldsm_x4(al[0][0], al[0][1], al[0][2], al[0][3], pA0 + 16384 + koA);
            ldsm_x4(al[1][0], al[1][1], al[1][2], al[1][3], pA1 + 16384 + koA);
            #pragma unroll
            for (int j16 = 0; j16 < 4; j16++) {
                uint32_t bh0, bh1, bh2, bh3, bl0, bl1, bl2, bl3;
                ldsm_x4(bh0, bh1, bh2, bh3, pB[j16] + koB);
                ldsm_x4(bl0, bl1, bl2, bl3, pB[j16] + 16384 + koB);
                #pragma unroll
                for (int i = 0; i < 2; i++) {
                    mma16816(acc[i][2*j16+0], ah[i][0], ah[i][1], ah[i][2], ah[i][3], bh0, bh1);
                    mma16816(acc[i][2*j16+0], al[i][0], al[i][1], al[i][2], al[i][3], bh0, bh1);
                    mma16816(acc[i][2*j16+0], ah[i][0], ah[i][1], ah[i][2], ah[i][3], bl0, bl1);
                    mma16816(acc[i][2*j16+1], ah[i][0], ah[i][1], ah[i][2], ah[i][3], bh2, bh3);
                    mma16816(acc[i][2*j16+1], al[i][0], al[i][1], al[i][2], al[i][3], bh2, bh3);
                    mma16816(acc[i][2*j16+1], ah[i][0], ah[i][1], ah[i][2], ah[i][3], bl2, bl3);
                }
            }
        }
        __syncthreads();
    }

    // ---- epilogue ----
    int qr = lane >> 2;          // quad row 0..7
    int qc = (lane & 3) << 1;    // col pair
    #pragma unroll
    for (int i = 0; i < 2; i++) {
        int r0 = m0 + wm + i * 16 + qr;
        #pragma unroll
        for (int j = 0; j < 8; j++) {
            int col = n0 + wn + j * 8 + qc;
            float b0 = __ldg(bias + col), b1 = __ldg(bias + col + 1);
            float2 v0, v1;
            v0.x = fmaxf(acc[i][j][0] + b0, 0.f);
            v0.y = fmaxf(acc[i][j][1] + b1, 0.f);
            v1.x = fmaxf(acc[i][j][2] + b0, 0.f);
            v1.y = fmaxf(acc[i][j][3] + b1, 0.f);
            *(float2*)(C + (size_t)r0 * 256 + col)       = v0;
            *(float2*)(C + (size_t)(r0 + 8) * 256 + col) = v1;
        }
    }
}

// ---------------- layer 2 + log_softmax ----------------
__global__ void layer2_logsoftmax_kernel(const float* __restrict__ agg,
                                         const float* __restrict__ W,
                                         const float* __restrict__ b,
                                         float* __restrict__ out) {
    __shared__ float a[256];
    __shared__ float logits[kNCls];
    __shared__ float s_ls;
    int row = blockIdx.x;
    int tid = threadIdx.x;
    const float4* ap = (const float4*)(agg + (size_t)row * 256);
    ((float4*)a)[tid] = ap[tid];
    __syncthreads();
    if (tid < kNCls) {
        float sum = b[tid];
        #pragma unroll 8
        for (int k = 0; k < 256; k++) sum += a[k] * W[k * kNCls + tid];
        logits[tid] = sum;
    }
    __syncthreads();
    if (tid == 0) {
        float m = -INFINITY;
        for (int j = 0; j < kNCls; j++) m = fmaxf(m, logits[j]);
        float s = 0.f;
        for (int j = 0; j < kNCls; j++) s += expf(logits[j] - m);
        s_ls = m + logf(s);
    }
    __syncthreads();
    if (tid < kNCls) out[(size_t)row * kNCls + tid] = logits[tid] - s_ls;
}

// ---------------- host launcher ----------------
extern "C" void kernel_launch(void* const* d_in, const int* in_sizes, int n_in,
                              void* d_out, int out_size) {
    const float* x    = (const float*)d_in[0];
    const float* W0   = (const float*)d_in[1];
    const float* b0   = (const float*)d_in[2];
    const float* W1   = (const float*)d_in[3];
    const float* b1   = (const float*)d_in[4];
    const float* W2   = (const float*)d_in[5];
    const float* b2   = (const float*)d_in[6];
    const int*   src0 = (const int*)d_in[7];
    const int*   dst0 = (const int*)d_in[8];
    const int*   src1 = (const int*)d_in[9];
    const int*   dst1 = (const int*)d_in[10];
    const int*   src2 = (const int*)d_in[11];
    const int*   dst2 = (const int*)d_in[12];
    float* out = (float*)d_out;

    float *h0, *h1, *agg2;
    __nv_bfloat16 *ahi, *alo, *w0h, *w0l, *w1h, *w1l;
    int *off0, *es0, *off1, *es1, *off2, *es2;
    cudaGetSymbolAddress((void**)&h0,   g_h0);
    cudaGetSymbolAddress((void**)&h1,   g_h1);
    cudaGetSymbolAddress((void**)&agg2, g_agg2);
    cudaGetSymbolAddress((void**)&ahi,  g_a_hi);
    cudaGetSymbolAddress((void**)&alo,  g_a_lo);
    cudaGetSymbolAddress((void**)&w0h,  g_w0h);
    cudaGetSymbolAddress((void**)&w0l,  g_w0l);
    cudaGetSymbolAddress((void**)&w1h,  g_w1h);
    cudaGetSymbolAddress((void**)&w1l,  g_w1l);
    cudaGetSymbolAddress((void**)&off0, g_off0);
    cudaGetSymbolAddress((void**)&es0,  g_es0);
    cudaGetSymbolAddress((void**)&off1, g_off1);
    cudaGetSymbolAddress((void**)&es1,  g_es1);
    cudaGetSymbolAddress((void**)&off2, g_off2);
    cudaGetSymbolAddress((void**)&es2,  g_es2);

    cudaFuncSetAttribute(gemm_mma_relu_kernel,
                         cudaFuncAttributeMaxDynamicSharedMemorySize, kGemmSmem);

    // CSR build + weight conversion (feature-independent prep)
    zero_counts_kernel<<<(kN0Dst + 255) / 256, 256>>>();
    hist3_kernel<<<(kE0 + 255) / 256, 256>>>(dst0, dst1, dst2);
    wconv_kernel<<<(2 * 65536) / 256, 256>>>(W0, W1);
    exscan3_kernel<<<3, 1024>>>();
    fill3_kernel<<<(kE0 + 255) / 256, 256>>>(src0, dst0, src1, dst1, src2, dst2);

    // Layer 0: aggregate -> bf16 hi/lo, tensor GEMM + relu
    aggregate_kernel<1><<<(kN0Dst * 32 + 255) / 256, 256>>>(x, off0, es0, nullptr, ahi, alo, kN0Dst);
    {
        dim3 grid(kN0Dst / 128, 2);
        gemm_mma_relu_kernel<<<grid, 256, kGemmSmem>>>(ahi, alo, w0h, w0l, b0, h0);
    }
    // Layer 1
    aggregate_kernel<1><<<(kN1Dst * 32 + 255) / 256, 256>>>(h0, off1, es1, nullptr, ahi, alo, kN1Dst);
    {
        dim3 grid(kN1Dst / 128, 2);
        gemm_mma_relu_kernel<<<grid, 256, kGemmSmem>>>(ahi, alo, w1h, w1l, b1, h1);
    }
    // Layer 2 + log_softmax (f32 SIMT; tiny)
    aggregate_kernel<0><<<(kN2Dst * 32 + 255) / 256, 256>>>(h1, off2, es2, agg2, nullptr, nullptr, kN2Dst);
    layer2_logsoftmax_kernel<<<kN2Dst, 64>>>(agg2, W2, b2, out);

    (void)in_sizes; (void)n_in; (void)out_size;
}